// round 2
// baseline (speedup 1.0000x reference)
#include <cuda_runtime.h>
#include <cuda_bf16.h>
#include <cstdint>

// Problem constants (fixed by the dataset): B=1024, T=512, K=64 tags.
#define KTAG 64
#define MAXB 1024
#define MAXT 512
#define NEGV -10000.0f

// Scratch tables (device globals: no allocation allowed in kernel_launch).
// g_fv[b][t][j] = viterbi value AFTER step t (max + emission)
// g_m [b][t][j] = max_prev(fv_prev + w[j][prev]) BEFORE emission (for backtrace
//                 equality-match argmax)
__device__ float g_fv[(size_t)MAXB * MAXT * KTAG];
__device__ float g_m [(size_t)MAXB * MAXT * KTAG];
__device__ int   g_last[MAXB];
__device__ float g_scratch[(size_t)MAXB * MAXT];
__device__ float g_scratch_score[MAXB];

// ============================================================================
// Forward: one block per batch, 64 threads (thread j owns "next" tag j).
// new_fv[j] = max_prev(fv[prev] + w[j][prev]) + feat[t][j]
// ============================================================================
__global__ __launch_bounds__(KTAG) void crf_forward(
    const float* __restrict__ feats,
    const float* __restrict__ weights,
    const int* __restrict__ lens,
    float* __restrict__ score_out,
    int T)
{
    const int b = blockIdx.x;
    const int j = threadIdx.x;          // next tag
    const int lane = j & 31;
    const int warp = j >> 5;

    // ping-pong fv buffers: one __syncthreads per step
    __shared__ __align__(16) float fv_sh[2][KTAG];
    __shared__ float red_v[2];
    __shared__ int   red_i[2];

    // Weight row w[j][0..63] in registers.
    float wreg[KTAG];
    {
        const float4* wrow = reinterpret_cast<const float4*>(weights + j * KTAG);
        #pragma unroll
        for (int i = 0; i < KTAG / 4; ++i) {
            float4 v = wrow[i];
            wreg[4 * i + 0] = v.x;
            wreg[4 * i + 1] = v.y;
            wreg[4 * i + 2] = v.z;
            wreg[4 * i + 3] = v.w;
        }
    }

    // init fv: NEG everywhere except START(=0).
    fv_sh[0][j] = (j == 0) ? 0.0f : NEGV;

    const int len = lens[b];            // 1..T
    const size_t base = (size_t)b * T * KTAG;

    // 4-deep emission prefetch ring.
    float fring[4];
    #pragma unroll
    for (int k = 0; k < 4; ++k)
        fring[k] = (k < T) ? feats[base + (size_t)k * KTAG + j] : 0.0f;

    __syncthreads();

    for (int t = 0; t < len; ++t) {
        const int rb = t & 1;

        float feat = fring[t & 3];
        if (t + 4 < T)
            fring[t & 3] = feats[base + (size_t)(t + 4) * KTAG + j];

        // max over prev: 64 FADD (fma pipe) + 64 FMNMX (alu pipe), 8 accs.
        float a0 = -3.0e38f, a1 = -3.0e38f, a2 = -3.0e38f, a3 = -3.0e38f;
        float a4 = -3.0e38f, a5 = -3.0e38f, a6 = -3.0e38f, a7 = -3.0e38f;
        const float4* fvv = reinterpret_cast<const float4*>(fv_sh[rb]);
        #pragma unroll
        for (int i = 0; i < 16; i += 2) {
            float4 f0 = fvv[i];
            float4 f1 = fvv[i + 1];
            a0 = fmaxf(a0, f0.x + wreg[4 * i + 0]);
            a1 = fmaxf(a1, f0.y + wreg[4 * i + 1]);
            a2 = fmaxf(a2, f0.z + wreg[4 * i + 2]);
            a3 = fmaxf(a3, f0.w + wreg[4 * i + 3]);
            a4 = fmaxf(a4, f1.x + wreg[4 * i + 4]);
            a5 = fmaxf(a5, f1.y + wreg[4 * i + 5]);
            a6 = fmaxf(a6, f1.z + wreg[4 * i + 6]);
            a7 = fmaxf(a7, f1.w + wreg[4 * i + 7]);
        }
        a0 = fmaxf(a0, a1); a2 = fmaxf(a2, a3);
        a4 = fmaxf(a4, a5); a6 = fmaxf(a6, a7);
        a0 = fmaxf(a0, a2); a4 = fmaxf(a4, a6);
        float maxv = fmaxf(a0, a4);
        float nf = maxv + feat;

        fv_sh[rb ^ 1][j] = nf;
        g_fv[base + (size_t)t * KTAG + j] = nf;
        g_m [base + (size_t)t * KTAG + j] = maxv;
        __syncthreads();
    }

    // Terminal: fv + weights[END=1][prev]; argmax, first-index tie-break.
    float v = fv_sh[len & 1][j] + weights[1 * KTAG + j];
    int idx = j;
    #pragma unroll
    for (int off = 16; off; off >>= 1) {
        float ov = __shfl_xor_sync(0xffffffffu, v, off);
        int   oi = __shfl_xor_sync(0xffffffffu, idx, off);
        if (ov > v || (ov == v && oi < idx)) { v = ov; idx = oi; }
    }
    if (lane == 0) { red_v[warp] = v; red_i[warp] = idx; }
    __syncthreads();
    if (j == 0) {
        float v0 = red_v[0], v1 = red_v[1];
        if (v1 > v0) { score_out[b] = v1; g_last[b] = red_i[1]; }
        else         { score_out[b] = v0; g_last[b] = red_i[0]; }
    }
}

// ============================================================================
// Backward: one warp per batch. Argmax recovered by equality match against
// the stored pre-emission max m[t][tag]:
//   tag' = first p with fv_after[t-1][p] + w[tag][p] == m[t][tag]
// (bit-exact: same FADD operands as forward; max is rounding-free).
// ============================================================================
#define CH 16   // timestep chunk staged to shared

__global__ __launch_bounds__(32) void crf_backward(
    const float* __restrict__ weights,
    const int* __restrict__ lens,
    float* __restrict__ path_out,
    int T)
{
    const int b = blockIdx.x;
    const int lane = threadIdx.x;

    __shared__ __align__(16) float w_sh[KTAG * KTAG];  // 16 KB
    __shared__ __align__(16) float fvbuf[CH * KTAG];   // 4 KB
    __shared__ __align__(16) float mbuf [CH * KTAG];   // 4 KB
    __shared__ float path_sh[MAXT];                    // 2 KB

    for (int q = lane; q < (KTAG * KTAG) / 4; q += 32)
        reinterpret_cast<float4*>(w_sh)[q] = reinterpret_cast<const float4*>(weights)[q];

    const int len = lens[b];
    int tag = g_last[b];
    const size_t base = (size_t)b * T * KTAG;
    __syncwarp();

    for (int hi = T; hi > 0; hi -= CH) {
        const int lo = hi - CH;
        __syncwarp();   // previous chunk's buffer reads complete

        // Stage fv rows r = lo-1+k (need fv_after[t-1], t in [lo,hi)) and
        //       m  rows rm = lo+k  (need m[t],        t in [lo,hi)).
        for (int q = lane; q < CH * (KTAG / 4); q += 32) {
            const int k = q >> 4;      // row within chunk
            const int c = q & 15;      // float4 column
            const int r = lo - 1 + k;
            if (r >= 0 && r <= len - 2)
                reinterpret_cast<float4*>(fvbuf)[q] =
                    reinterpret_cast<const float4*>(g_fv + base + (size_t)r * KTAG)[c];
            const int rm = lo + k;
            if (rm >= 1 && rm <= len - 1)
                reinterpret_cast<float4*>(mbuf)[q] =
                    reinterpret_cast<const float4*>(g_m + base + (size_t)rm * KTAG)[c];
        }
        __syncwarp();

        for (int t = hi - 1; t >= lo; --t) {
            if (lane == 0) path_sh[t] = (float)tag;
            if (t >= 1 && t < len) {
                const float target = mbuf[(t - lo) * KTAG + tag];
                const float* fr = fvbuf + (t - lo) * KTAG;
                const float* wr = w_sh + tag * KTAG;
                const bool p0 = (fr[lane]      + wr[lane])      == target;
                const bool p1 = (fr[lane + 32] + wr[lane + 32]) == target;
                const unsigned b0 = __ballot_sync(0xffffffffu, p0);
                const unsigned b1 = __ballot_sync(0xffffffffu, p1);
                tag = b0 ? (__ffs(b0) - 1) : (__ffs(b1) + 31);
            }
        }
    }
    __syncwarp();

    for (int q = lane; q < T; q += 32)
        path_out[(size_t)b * T + q] = path_sh[q];
}

extern "C" void kernel_launch(void* const* d_in, const int* in_sizes, int n_in,
                              void* d_out, int out_size) {
    const float* feats   = (const float*)d_in[0];
    const float* weights = (const float*)d_in[1];
    const int*   lens    = (const int*)d_in[2];

    const int B = in_sizes[2];
    const int K = KTAG;
    const int T = in_sizes[0] / (B * K);

    float* out = (float*)d_out;
    float* score_ptr;
    float* path_ptr;

    if (out_size == B * (T + 1)) {          // [score B | paths B*T]
        score_ptr = out;
        path_ptr  = out + B;
    } else if (out_size == B) {             // score only
        score_ptr = out;
        void* p; cudaGetSymbolAddress(&p, g_scratch);
        path_ptr = (float*)p;
    } else {                                // paths only
        path_ptr = out;
        void* p; cudaGetSymbolAddress(&p, g_scratch_score);
        score_ptr = (float*)p;
    }

    crf_forward<<<B, KTAG>>>(feats, weights, lens, score_ptr, T);
    crf_backward<<<B, 32>>>(weights, lens, path_ptr, T);
}